// round 5
// baseline (speedup 1.0000x reference)
#include <cuda_runtime.h>
#include <cstdint>

// ---------------------------------------------------------------------------
// LSTM cell, sm_103 base target. R5: 384 threads / 12 warps, warp tile
// Mw=64 x Nw=32 (flat N across 3 gates) to balance ldmatrix crossbar traffic
// (~1150 cyc/stage) against the HMMA floor (~1460 cyc/stage), 3 warps/SMSP.
// Epilogue gathers gates via smem staging (warps no longer own all 3 gates).
// tf32 rounding hoisted to prepass kernels (g_X, g_W device scratch).
// ---------------------------------------------------------------------------

static constexpr int BATCH = 16384;
static constexpr int HID   = 1024;
static constexpr int KTOT  = 2048;
static constexpr int BM    = 128;
static constexpr int BN_G  = 64;     // per gate
static constexpr int NF    = 192;    // flat N = 3 gates x 64
static constexpr int BK    = 32;
static constexpr int KSTEPS = KTOT / BK;   // 64
static constexpr int NSTAGE = 4;
static constexpr int NTHR   = 384;

static constexpr uint32_t A_ST  = BM * 128;   // 16 KB
static constexpr uint32_t B_ST  = NF * 128;   // 24 KB
static constexpr uint32_t STAGE = A_ST + B_ST; // 40 KB
static constexpr uint32_t SMEM_BYTES = NSTAGE * STAGE + 2048;

static constexpr int GSTRIDE = 196;  // floats; padded row stride for gate staging

__device__ float g_X[(long)BATCH * KTOT];       // tf32-rounded [x|h]
__device__ float g_W[(long)3 * HID * KTOT];     // tf32-rounded gate-concat W

__device__ __forceinline__ uint32_t smem_u32(const void* p) {
    uint32_t a;
    asm("{ .reg .u64 t; cvta.to.shared.u64 t, %1; cvt.u32.u64 %0, t; }"
        : "=r"(a) : "l"(p));
    return a;
}

#define CP_ASYNC16(dst, src) \
    asm volatile("cp.async.cg.shared.global [%0], [%1], 16;" :: "r"(dst), "l"(src) : "memory")
#define CP_COMMIT() asm volatile("cp.async.commit_group;" ::: "memory")

#define LDSM4(r, addr)                                                         \
    asm volatile("ldmatrix.sync.aligned.m8n8.x4.shared.b16 {%0,%1,%2,%3}, [%4];" \
        : "=r"((r)[0]), "=r"((r)[1]), "=r"((r)[2]), "=r"((r)[3]) : "r"(addr))

#define MMA_TF32(d, a, b0, b1)                                                 \
    asm volatile("mma.sync.aligned.m16n8k8.row.col.f32.tf32.tf32.f32 "         \
        "{%0,%1,%2,%3},{%4,%5,%6,%7},{%8,%9},{%0,%1,%2,%3};"                   \
        : "+f"((d)[0]), "+f"((d)[1]), "+f"((d)[2]), "+f"((d)[3])               \
        : "r"((a)[0]), "r"((a)[1]), "r"((a)[2]), "r"((a)[3]), "r"(b0), "r"(b1))

__device__ __forceinline__ float f2tf_f(float v) {
    uint32_t o;
    asm("cvt.rna.tf32.f32 %0, %1;" : "=r"(o) : "r"(__float_as_uint(v)));
    return __uint_as_float(o);
}

__device__ __forceinline__ float4 round4(float4 v) {
    v.x = f2tf_f(v.x); v.y = f2tf_f(v.y); v.z = f2tf_f(v.z); v.w = f2tf_f(v.w);
    return v;
}

// ---- prepass ---------------------------------------------------------------
__global__ __launch_bounds__(256)
void prep_x_kernel(const float* __restrict__ x, const float* __restrict__ h) {
    const long i = (long)blockIdx.x * 256 + threadIdx.x;
    const long row = i >> 9;
    const int  c4  = (int)(i & 511);
    float4 v = (c4 < 256) ? ((const float4*)x)[row * 256 + c4]
                          : ((const float4*)h)[row * 256 + (c4 - 256)];
    ((float4*)g_X)[i] = round4(v);
}

__global__ __launch_bounds__(256)
void prep_w_kernel(const float* __restrict__ Wii, const float* __restrict__ Whi,
                   const float* __restrict__ Wif, const float* __restrict__ Whf,
                   const float* __restrict__ Wig, const float* __restrict__ Whg) {
    const long i = (long)blockIdx.x * 256 + threadIdx.x;
    const long grow = i >> 9;
    const int  c4   = (int)(i & 511);
    const int  g    = (int)(grow >> 10);
    const long r    = grow & 1023;
    const float* Wx = (g == 0) ? Wii : (g == 1) ? Wif : Wig;
    const float* Wh = (g == 0) ? Whi : (g == 1) ? Whf : Whg;
    float4 v = (c4 < 256) ? ((const float4*)Wx)[r * 256 + c4]
                          : ((const float4*)Wh)[r * 256 + (c4 - 256)];
    ((float4*)g_W)[i] = round4(v);
}

__device__ __forceinline__ float lstm_elem(float gi, float gf, float gg,
                                           float bi, float bf, float bg, float cv) {
    float vi = gi + bi;
    float vf = gf + bf;
    float vg = gg + bg;
    float si = 1.0f / (1.0f + __expf(-vi));
    float sf = 1.0f / (1.0f + __expf(-vf));
    float vgc = fminf(15.0f, fmaxf(-15.0f, vg));
    float e2  = __expf(2.0f * vgc);
    float tg  = (e2 - 1.0f) / (e2 + 1.0f);
    return fmaf(sf, cv, si * tg);
}

__global__ __launch_bounds__(NTHR, 1)
void lstm_mma_kernel(const float* __restrict__ c,
                     const float* __restrict__ bii, const float* __restrict__ bhi,
                     const float* __restrict__ bif, const float* __restrict__ bhf,
                     const float* __restrict__ big, const float* __restrict__ bhg,
                     float* __restrict__ out) {
    extern __shared__ char smem_raw[];
    const uint32_t raw   = smem_u32(smem_raw);
    const uint32_t tiles = (raw + 1023u) & ~1023u;
    float* Gs   = (float*)(smem_raw + (tiles - raw));               // reuses stage mem
    float* bias = (float*)(smem_raw + (tiles - raw) + NSTAGE * STAGE);

    const int tid  = threadIdx.x;
    const int lane = tid & 31;
    const int wid  = tid >> 5;
    const int wm   = wid >> 2;      // 0..2 -> *wrong*; see below
    // 12 warps: wm (0..1) x wj (0..5)
    const int wmm  = wid / 6;       // 0..1 : M half (64 rows)
    const int wj   = wid % 6;       // 0..5 : 32 flat-N cols
    (void)wm;

    const int m0 = (int)(blockIdx.x >> 4) * BM;
    const int n0 = (int)(blockIdx.x & 15) * BN_G;

    if (tid < 192) {
        const int g = tid >> 6, j = tid & 63, n = n0 + j;
        float v;
        if (g == 0)      v = bii[n] + bhi[n];
        else if (g == 1) v = bif[n] + bhf[n];
        else             v = big[n] + bhg[n];
        bias[tid] = v;
    }

    // producer invariants ----------------------------------------------------
    uint32_t aoffs[3]; const float* asrc[3]; bool aval[3];
    #pragma unroll
    for (int i = 0; i < 3; ++i) {
        const int id = tid + i * NTHR;
        aval[i] = (id < BM * 8);
        const int row = id >> 3, ch = id & 7;
        aoffs[i] = (uint32_t)(row * 128 + ((ch ^ (row & 7)) << 4));
        asrc[i]  = g_X + (long)(m0 + (aval[i] ? row : 0)) * KTOT + ch * 4;
    }
    uint32_t boffs[4]; const float* bsrc[4];
    #pragma unroll
    for (int i = 0; i < 4; ++i) {
        const int id = tid + i * NTHR;       // 0..1535
        const int grow = id >> 3, ch = id & 7;
        const int g = grow >> 6, r = grow & 63;
        boffs[i] = (uint32_t)(grow * 128 + ((ch ^ (r & 7)) << 4));
        bsrc[i]  = g_W + (long)(g * HID + n0 + r) * KTOT + ch * 4;
    }

    // consumer invariants ----------------------------------------------------
    const uint32_t s7 = (uint32_t)(lane & 7);
    const int lmrow = (lane & 7) + ((lane >> 3) & 1) * 8;
    const int lkh   = lane >> 4;
    uint32_t arow[4], brow[2];
    #pragma unroll
    for (int mt = 0; mt < 4; ++mt)
        arow[mt] = (uint32_t)((wmm * 64 + mt * 16 + lmrow) * 128);
    #pragma unroll
    for (int bt = 0; bt < 2; ++bt)
        brow[bt] = (uint32_t)((wj * 32 + bt * 16 + lmrow) * 128);

    float acc[4][4][4];   // [mt][ng = bt*2+p][quad]
    #pragma unroll
    for (int mt = 0; mt < 4; ++mt)
        #pragma unroll
        for (int ng = 0; ng < 4; ++ng)
            #pragma unroll
            for (int q = 0; q < 4; ++q) acc[mt][ng][q] = 0.0f;

    auto load_stage = [&](int s, int ks) {
        const int kk = ks * BK;
        const uint32_t sAs = tiles + (uint32_t)s * STAGE;
        const uint32_t sBs = sAs + A_ST;
        #pragma unroll
        for (int i = 0; i < 3; ++i)
            if (aval[i]) CP_ASYNC16(sAs + aoffs[i], asrc[i] + kk);
        #pragma unroll
        for (int i = 0; i < 4; ++i)
            CP_ASYNC16(sBs + boffs[i], bsrc[i] + kk);
    };

    #pragma unroll
    for (int s = 0; s < NSTAGE - 1; ++s) { load_stage(s, s); CP_COMMIT(); }

    for (int ks = 0; ks < KSTEPS; ++ks) {
        asm volatile("cp.async.wait_group %0;" :: "n"(NSTAGE - 2));
        __syncthreads();

        const uint32_t sAs = tiles + (uint32_t)(ks & (NSTAGE - 1)) * STAGE;
        const uint32_t sBs = sAs + A_ST;

        // fragment double-buffer across kst
        uint32_t a[2][4][4], b[2][2][4];
        {
            const uint32_t off0 = (uint32_t)((lkh ^ s7) << 4);
            #pragma unroll
            for (int mt = 0; mt < 4; ++mt) LDSM4(a[0][mt], sAs + arow[mt] + off0);
            #pragma unroll
            for (int bt = 0; bt < 2; ++bt) LDSM4(b[0][bt], sBs + brow[bt] + off0);
        }
        #pragma unroll
        for (int kst = 0; kst < 4; ++kst) {
            const int cur = kst & 1, nxt = cur ^ 1;
            if (kst < 3) {
                const uint32_t off = (uint32_t)((((kst + 1) * 2 + lkh) ^ s7) << 4);
                #pragma unroll
                for (int mt = 0; mt < 4; ++mt) LDSM4(a[nxt][mt], sAs + arow[mt] + off);
                #pragma unroll
                for (int bt = 0; bt < 2; ++bt) LDSM4(b[nxt][bt], sBs + brow[bt] + off);
            }
            #pragma unroll
            for (int bt = 0; bt < 2; ++bt)
                #pragma unroll
                for (int p = 0; p < 2; ++p)
                    #pragma unroll
                    for (int mt = 0; mt < 4; ++mt)
                        MMA_TF32(acc[mt][bt * 2 + p], a[cur][mt],
                                 b[cur][bt][p], b[cur][bt][p + 2]);
        }

        const int pf = ks + NSTAGE - 1;
        if (pf < KSTEPS) load_stage(pf & (NSTAGE - 1), pf);
        CP_COMMIT();
    }

    // ---- epilogue: stage gates through smem, then gather all 3 per elem ----
    __syncthreads();   // all MMAs done; stage buffers are dead, reuse as Gs
    {
        const int rbase = wmm * 64 + (lane >> 2);
        const int cbase = wj * 32 + (lane & 3) * 2;
        #pragma unroll
        for (int mt = 0; mt < 4; ++mt)
            #pragma unroll
            for (int ng = 0; ng < 4; ++ng)
                #pragma unroll
                for (int rh = 0; rh < 2; ++rh) {
                    const int rr = rbase + mt * 16 + rh * 8;
                    const int cc = cbase + ng * 8;
                    float2 v = make_float2(acc[mt][ng][rh * 2],
                                           acc[mt][ng][rh * 2 + 1]);
                    *(float2*)(Gs + rr * GSTRIDE + cc) = v;
                }
    }
    __syncthreads();

    for (int idx = tid; idx < BM * BN_G; idx += NTHR) {
        const int m = idx >> 6, n = idx & 63;
        const float gi = Gs[m * GSTRIDE + n];
        const float gf = Gs[m * GSTRIDE + 64 + n];
        const float gg = Gs[m * GSTRIDE + 128 + n];
        const long  go = (long)(m0 + m) * HID + n0 + n;
        out[go] = lstm_elem(gi, gf, gg, bias[n], bias[64 + n], bias[128 + n], c[go]);
    }
}

extern "C" void kernel_launch(void* const* d_in, const int* in_sizes, int n_in,
                              void* d_out, int out_size) {
    const float* x   = (const float*)d_in[0];
    const float* h   = (const float*)d_in[1];
    const float* c   = (const float*)d_in[2];
    const float* Wii = (const float*)d_in[3];
    const float* bii = (const float*)d_in[4];
    const float* Whi = (const float*)d_in[5];
    const float* bhi = (const float*)d_in[6];
    const float* Wif = (const float*)d_in[7];
    const float* bif = (const float*)d_in[8];
    const float* Whf = (const float*)d_in[9];
    const float* bhf = (const float*)d_in[10];
    const float* Wig = (const float*)d_in[11];
    const float* big = (const float*)d_in[12];
    const float* Whg = (const float*)d_in[13];
    const float* bhg = (const float*)d_in[14];
    float* out = (float*)d_out;

    cudaFuncSetAttribute(lstm_mma_kernel,
                         cudaFuncAttributeMaxDynamicSharedMemorySize, SMEM_BYTES);

    prep_x_kernel<<<(long)BATCH * KTOT / 4 / 256, 256>>>(x, h);
    prep_w_kernel<<<(long)3 * HID * KTOT / 4 / 256, 256>>>(
        Wii, Whi, Wif, Whf, Wig, Whg);

    dim3 grid((BATCH / BM) * (HID / BN_G));
    lstm_mma_kernel<<<grid, NTHR, SMEM_BYTES>>>(
        c, bii, bhi, bif, bhf, big, bhg, out);
}

// round 6
// speedup vs baseline: 1.9971x; 1.9971x over previous
#include <cuda_runtime.h>
#include <cuda_fp16.h>
#include <cstdint>

// ---------------------------------------------------------------------------
// LSTM cell, sm_103 base target. R6: fp16 m16n8k16 MMA (11-bit significand ==
// tf32 precision, fp32 accumulate) — halves MMA instruction count, smem
// traffic, and cp.async traffic vs the tf32 path. Prepass rounds f32 -> half
// into g_X ([x|h]) and g_W (gate-concat). 8 warps, Mw64 x Nw48 (R2/R3 proven
// geometry), register-resident 3-gate epilogue.
// ---------------------------------------------------------------------------

static constexpr int BATCH = 16384;
static constexpr int HID   = 1024;
static constexpr int KTOT  = 2048;
static constexpr int BM    = 128;
static constexpr int BN_G  = 64;
static constexpr int GATES = 3;
static constexpr int BK    = 64;           // K per stage (64 halfs = 128B row)
static constexpr int KSTEPS = KTOT / BK;   // 32
static constexpr int NSTAGE = 4;
static constexpr int NTHR   = 256;

static constexpr uint32_t A_ST  = BM * 128;            // 16 KB
static constexpr uint32_t B_ST  = GATES * BN_G * 128;  // 24 KB
static constexpr uint32_t STAGE = A_ST + B_ST;         // 40 KB
static constexpr uint32_t SMEM_BYTES = NSTAGE * STAGE + 1024;

__device__ __half g_X[(long)BATCH * KTOT];          // 67 MB
__device__ __half g_W[(long)GATES * HID * KTOT];    // 12.6 MB

__device__ __forceinline__ uint32_t smem_u32(const void* p) {
    uint32_t a;
    asm("{ .reg .u64 t; cvta.to.shared.u64 t, %1; cvt.u32.u64 %0, t; }"
        : "=r"(a) : "l"(p));
    return a;
}

#define CP_ASYNC16(dst, src) \
    asm volatile("cp.async.cg.shared.global [%0], [%1], 16;" :: "r"(dst), "l"(src) : "memory")
#define CP_COMMIT() asm volatile("cp.async.commit_group;" ::: "memory")

#define LDSM4(r, addr)                                                         \
    asm volatile("ldmatrix.sync.aligned.m8n8.x4.shared.b16 {%0,%1,%2,%3}, [%4];" \
        : "=r"((r)[0]), "=r"((r)[1]), "=r"((r)[2]), "=r"((r)[3]) : "r"(addr))

#define MMA_F16(d, a, b0, b1)                                                  \
    asm volatile("mma.sync.aligned.m16n8k16.row.col.f32.f16.f16.f32 "          \
        "{%0,%1,%2,%3},{%4,%5,%6,%7},{%8,%9},{%0,%1,%2,%3};"                   \
        : "+f"((d)[0]), "+f"((d)[1]), "+f"((d)[2]), "+f"((d)[3])               \
        : "r"((a)[0]), "r"((a)[1]), "r"((a)[2]), "r"((a)[3]), "r"(b0), "r"(b1))

// ---- prepass: f32 -> half, concatenated layouts ---------------------------
__global__ __launch_bounds__(256)
void prep_x_kernel(const float* __restrict__ x, const float* __restrict__ h) {
    // each thread: 8 elements (two float4 reads, one 16B half8 write)
    const long i = (long)blockIdx.x * 256 + threadIdx.x;   // half8 index
    const long row = i >> 8;                               // 256 half8 per row
    const int  c8  = (int)(i & 255);                       // 0..255 (8-elem chunk)
    const float4* src = (c8 < 128) ? (const float4*)(x + row * 1024 + c8 * 8)
                                   : (const float4*)(h + row * 1024 + (c8 - 128) * 8);
    const float4 v0 = src[0], v1 = src[1];
    __half2 o[4];
    o[0] = __floats2half2_rn(v0.x, v0.y);
    o[1] = __floats2half2_rn(v0.z, v0.w);
    o[2] = __floats2half2_rn(v1.x, v1.y);
    o[3] = __floats2half2_rn(v1.z, v1.w);
    ((uint4*)g_X)[i] = *(const uint4*)o;
}

__global__ __launch_bounds__(256)
void prep_w_kernel(const float* __restrict__ Wii, const float* __restrict__ Whi,
                   const float* __restrict__ Wif, const float* __restrict__ Whf,
                   const float* __restrict__ Wig, const float* __restrict__ Whg) {
    const long i = (long)blockIdx.x * 256 + threadIdx.x;   // half8 index
    const long grow = i >> 8;                              // 0..3071
    const int  c8   = (int)(i & 255);
    const int  g    = (int)(grow >> 10);
    const long r    = grow & 1023;
    const float* Wx = (g == 0) ? Wii : (g == 1) ? Wif : Wig;
    const float* Wh = (g == 0) ? Whi : (g == 1) ? Whf : Whg;
    const float4* src = (c8 < 128) ? (const float4*)(Wx + r * 1024 + c8 * 8)
                                   : (const float4*)(Wh + r * 1024 + (c8 - 128) * 8);
    const float4 v0 = src[0], v1 = src[1];
    __half2 o[4];
    o[0] = __floats2half2_rn(v0.x, v0.y);
    o[1] = __floats2half2_rn(v0.z, v0.w);
    o[2] = __floats2half2_rn(v1.x, v1.y);
    o[3] = __floats2half2_rn(v1.z, v1.w);
    ((uint4*)g_W)[i] = *(const uint4*)o;
}

__device__ __forceinline__ float lstm_elem(float gi, float gf, float gg,
                                           float bi, float bf, float bg, float cv) {
    float vi = gi + bi;
    float vf = gf + bf;
    float vg = gg + bg;
    float si = 1.0f / (1.0f + __expf(-vi));
    float sf = 1.0f / (1.0f + __expf(-vf));
    float vgc = fminf(15.0f, fmaxf(-15.0f, vg));
    float e2  = __expf(2.0f * vgc);
    float tg  = (e2 - 1.0f) / (e2 + 1.0f);
    return fmaf(sf, cv, si * tg);
}

__global__ __launch_bounds__(NTHR, 1)
void lstm_mma_kernel(const float* __restrict__ c,
                     const float* __restrict__ bii, const float* __restrict__ bhi,
                     const float* __restrict__ bif, const float* __restrict__ bhf,
                     const float* __restrict__ big, const float* __restrict__ bhg,
                     float* __restrict__ out) {
    extern __shared__ char smem_raw[];
    const uint32_t raw   = smem_u32(smem_raw);
    const uint32_t tiles = (raw + 1023u) & ~1023u;
    float* bias = (float*)(smem_raw + (tiles - raw) + NSTAGE * STAGE);

    const int tid  = threadIdx.x;
    const int lane = tid & 31;
    const int wid  = tid >> 5;
    const int wm   = wid >> 2;      // 0..1  (64 rows)
    const int wn   = wid & 3;       // 0..3  (16 cols per gate)

    const int m0 = (int)(blockIdx.x >> 4) * BM;
    const int n0 = (int)(blockIdx.x & 15) * BN_G;

    if (tid < 192) {
        const int g = tid >> 6, j = tid & 63, n = n0 + j;
        float v;
        if (g == 0)      v = bii[n] + bhi[n];
        else if (g == 1) v = bif[n] + bhf[n];
        else             v = big[n] + bhg[n];
        bias[tid] = v;
    }

    // ---- producer invariants: 16B chunks, row = 128B (64 halfs) -----------
    // A: 128 rows x 8 chunks = 1024 chunks -> 4 per thread
    uint32_t aoffs[4]; const __half* asrc[4];
    #pragma unroll
    for (int i = 0; i < 4; ++i) {
        const int id = tid + i * NTHR;
        const int row = id >> 3, ch = id & 7;
        aoffs[i] = (uint32_t)(row * 128 + ((ch ^ (row & 7)) << 4));
        asrc[i]  = g_X + (long)(m0 + row) * KTOT + ch * 8;
    }
    // B: 192 rows x 8 chunks = 1536 chunks -> 6 per thread
    uint32_t boffs[6]; const __half* bsrc[6];
    #pragma unroll
    for (int i = 0; i < 6; ++i) {
        const int id = tid + i * NTHR;
        const int grow = id >> 3, ch = id & 7;
        const int g = grow >> 6, r = grow & 63;
        boffs[i] = (uint32_t)(grow * 128 + ((ch ^ (r & 7)) << 4));
        bsrc[i]  = g_W + (long)(g * HID + n0 + r) * KTOT + ch * 8;
    }

    // ---- consumer ldmatrix invariants -------------------------------------
    // A (m16n8k16 a-frag via x4 non-trans): row=(l&7)+((l>>3)&1)*8, kchunk=(l>>4)
    const int a_r  = (lane & 7) + ((lane >> 3) & 1) * 8;
    const int a_kx = lane >> 4;                       // 0/1 -> +16B
    // B (two n8 tiles per x4 non-trans): nrow=(l&7)+((l>>4)<<3), kchunk=(l>>3)&1
    const int b_r  = (lane & 7) + ((lane >> 4) << 3);
    const int b_kx = (lane >> 3) & 1;

    uint32_t arow[4], brow[GATES];
    #pragma unroll
    for (int mt = 0; mt < 4; ++mt)
        arow[mt] = (uint32_t)((wm * 64 + mt * 16 + a_r) * 128);
    #pragma unroll
    for (int g = 0; g < GATES; ++g)
        brow[g] = (uint32_t)((g * 64 + wn * 16 + b_r) * 128);

    const uint32_t a_s7 = (uint32_t)(a_r & 7);
    const uint32_t b_s7 = (uint32_t)(b_r & 7);

    float acc[GATES][4][2][4];
    #pragma unroll
    for (int g = 0; g < GATES; ++g)
        #pragma unroll
        for (int mt = 0; mt < 4; ++mt)
            #pragma unroll
            for (int nt = 0; nt < 2; ++nt)
                #pragma unroll
                for (int q = 0; q < 4; ++q) acc[g][mt][nt][q] = 0.0f;

    auto load_stage = [&](int s, int ks) {
        const int kk = ks * BK;                       // halfs
        const uint32_t sAs = tiles + (uint32_t)s * STAGE;
        const uint32_t sBs = sAs + A_ST;
        #pragma unroll
        for (int i = 0; i < 4; ++i)
            CP_ASYNC16(sAs + aoffs[i], asrc[i] + kk);
        #pragma unroll
        for (int i = 0; i < 6; ++i)
            CP_ASYNC16(sBs + boffs[i], bsrc[i] + kk);
    };

    #pragma unroll
    for (int s = 0; s < NSTAGE - 1; ++s) { load_stage(s, s); CP_COMMIT(); }

    for (int ks = 0; ks < KSTEPS; ++ks) {
        asm volatile("cp.async.wait_group %0;" :: "n"(NSTAGE - 2));
        __syncthreads();

        const uint32_t sAs = tiles + (uint32_t)(ks & (NSTAGE - 1)) * STAGE;
        const uint32_t sBs = sAs + A_ST;

        #pragma unroll
        for (int kst = 0; kst < 4; ++kst) {           // 4 x K16 per stage
            const uint32_t aoff = (uint32_t)((((kst * 2 + a_kx)) ^ a_s7) << 4);
            const uint32_t boff = (uint32_t)((((kst * 2 + b_kx)) ^ b_s7) << 4);
            uint32_t a[4][4], b[GATES][4];
            #pragma unroll
            for (int mt = 0; mt < 4; ++mt) LDSM4(a[mt], sAs + arow[mt] + aoff);
            #pragma unroll
            for (int g = 0; g < GATES; ++g) LDSM4(b[g], sBs + brow[g] + boff);
            #pragma unroll
            for (int g = 0; g < GATES; ++g)
                #pragma unroll
                for (int mt = 0; mt < 4; ++mt) {
                    MMA_F16(acc[g][mt][0], a[mt], b[g][0], b[g][1]);
                    MMA_F16(acc[g][mt][1], a[mt], b[g][2], b[g][3]);
                }
        }

        const int pf = ks + NSTAGE - 1;
        if (pf < KSTEPS) load_stage(pf & (NSTAGE - 1), pf);
        CP_COMMIT();
    }

    // ---- epilogue: register-resident --------------------------------------
    #pragma unroll
    for (int mt = 0; mt < 4; ++mt) {
        const int mrow = m0 + wm * 64 + mt * 16 + (lane >> 2);
        #pragma unroll
        for (int nt = 0; nt < 2; ++nt) {
            const int nl = wn * 16 + nt * 8 + (lane & 3) * 2;
            const float bi0 = bias[nl],       bi1 = bias[nl + 1];
            const float bf0 = bias[64 + nl],  bf1 = bias[64 + nl + 1];
            const float bg0 = bias[128 + nl], bg1 = bias[128 + nl + 1];
            #pragma unroll
            for (int rh = 0; rh < 2; ++rh) {
                const long idx = (long)(mrow + rh * 8) * HID + n0 + nl;
                const float2 cv = *(const float2*)(c + idx);
                float2 ov;
                ov.x = lstm_elem(acc[0][mt][nt][rh * 2],
                                 acc[1][mt][nt][rh * 2],
                                 acc[2][mt][nt][rh * 2], bi0, bf0, bg0, cv.x);
                ov.y = lstm_elem(acc[0][mt][nt][rh * 2 + 1],
                                 acc[1][mt][nt][rh * 2 + 1],
                                 acc[2][mt][nt][rh * 2 + 1], bi1, bf1, bg1, cv.y);
                *(float2*)(out + idx) = ov;
            }
        }
    }
}

extern "C" void kernel_launch(void* const* d_in, const int* in_sizes, int n_in,
                              void* d_out, int out_size) {
    const float* x   = (const float*)d_in[0];
    const float* h   = (const float*)d_in[1];
    const float* c   = (const float*)d_in[2];
    const float* Wii = (const float*)d_in[3];
    const float* bii = (const float*)d_in[4];
    const float* Whi = (const float*)d_in[5];
    const float* bhi = (const float*)d_in[6];
    const float* Wif = (const float*)d_in[7];
    const float* bif = (const float*)d_in[8];
    const float* Whf = (const float*)d_in[9];
    const float* bhf = (const float*)d_in[10];
    const float* Wig = (const float*)d_in[11];
    const float* big = (const float*)d_in[12];
    const float* Whg = (const float*)d_in[13];
    const float* bhg = (const float*)d_in[14];
    float* out = (float*)d_out;

    cudaFuncSetAttribute(lstm_mma_kernel,
                         cudaFuncAttributeMaxDynamicSharedMemorySize, SMEM_BYTES);

    prep_x_kernel<<<(long)BATCH * KTOT / 8 / 256, 256>>>(x, h);
    prep_w_kernel<<<(long)GATES * HID * KTOT / 8 / 256, 256>>>(
        Wii, Whi, Wif, Whf, Wig, Whg);

    dim3 grid((BATCH / BM) * (HID / BN_G));
    lstm_mma_kernel<<<grid, NTHR, SMEM_BYTES>>>(
        c, bii, bhi, bif, bhf, big, bhg, out);
}